// round 14
// baseline (speedup 1.0000x reference)
#include <cuda_runtime.h>
#include <math.h>

#define NMAX 50000
#define DD 128
#define EMAX 700000
#define TR 64            // GEMM rows per block
#define ALPHA 0.2f

// ---------------- scratch (device globals, no runtime alloc) ----------------
// NOTE: g_deg is zero at module load, and scan23_kernel re-zeros it after its
// last read, so every kernel_launch call starts with g_deg == 0.
__device__ float g_h[NMAX * DD];      // h = X @ W
__device__ float g_ssrc[NMAX];        // h . a[:D]
__device__ float g_sdst[NMAX];        // h . a[D:]
__device__ int   g_deg[NMAX];
__device__ int   g_rowptr[NMAX + 1];
__device__ int   g_cursor[NMAX];
__device__ int   g_edst[EMAX];        // CSR-sorted dst
__device__ int   g_part[256];         // block partial sums for scan

// ---------------- side stream + fork/join events (created once, pre-main) --
static cudaStream_t g_s2;
static cudaEvent_t  g_evFork, g_evJoin;
static struct StreamInit {
    StreamInit() {
        cudaStreamCreateWithFlags(&g_s2, cudaStreamNonBlocking);
        cudaEventCreateWithFlags(&g_evFork, cudaEventDisableTiming);
        cudaEventCreateWithFlags(&g_evJoin, cudaEventDisableTiming);
    }
} g_streamInit;

// ---------------- per-block int64 detection ---------------------------------
// int64 little-endian: odd 32-bit words are high words (zero for ids < 2^31).
// int32: odd words are real node ids -- 256 consecutive zeros is impossible
// for random edges. Each block decides independently (no extra kernel).
__device__ __forceinline__ int detect_is64_block(const int* __restrict__ e32, int E) {
    int tid = threadIdx.x;
    int j = 2 * tid + 1;
    int v = (j < 2 * E && tid < 256) ? e32[j] : 0;
    return __syncthreads_or(v != 0) ? 0 : 1;
}

// ---------------- GEMM + attention projections (packed f32x2 FFMA) ----------
// block: 256 threads, computes TR=64 rows x 128 cols.
// smem: W[128][128] (64KB) + X tile[64][128] (32KB) = 96KB dynamic.
__global__ void __launch_bounds__(256, 2)
gemm_kernel(const float* __restrict__ X, const float* __restrict__ W,
            const float* __restrict__ a, int n) {
    extern __shared__ float smem[];
    float* Ws = smem;                 // 128*128
    float* Xs = smem + DD * DD;       // 64*128
    const int base = blockIdx.x * TR;
    const int tid = threadIdx.x;

    for (int i = tid * 4; i < DD * DD; i += blockDim.x * 4)
        *(float4*)&Ws[i] = *(const float4*)&W[i];
    for (int i = tid * 4; i < TR * DD; i += blockDim.x * 4) {
        int row = base + i / DD;
        float4 v = make_float4(0.f, 0.f, 0.f, 0.f);
        if (row < n) v = *(const float4*)&X[row * DD + (i % DD)];
        *(float4*)&Xs[i] = v;
    }
    __syncthreads();

    const int lane = tid & 31;
    const int wid = tid >> 5;         // 8 warps
    const int c4 = lane * 4;          // warp covers all 128 cols
    const int r0 = wid * 8;           // 8 rows per warp

    unsigned long long acc0[8], acc1[8];   // packed (f32,f32) accumulators
#pragma unroll
    for (int r = 0; r < 8; ++r) { acc0[r] = 0ull; acc1[r] = 0ull; }

    for (int k = 0; k < DD; k += 4) {
        float4 xv[8];
#pragma unroll
        for (int r = 0; r < 8; ++r)
            xv[r] = *(const float4*)&Xs[(r0 + r) * DD + k];   // broadcast within warp
#pragma unroll
        for (int kk = 0; kk < 4; ++kk) {
            ulonglong2 wp = *(const ulonglong2*)&Ws[(k + kk) * DD + c4];
#pragma unroll
            for (int r = 0; r < 8; ++r) {
                float x = (kk == 0) ? xv[r].x : (kk == 1) ? xv[r].y
                         : (kk == 2) ? xv[r].z : xv[r].w;
                unsigned long long xx;
                asm("mov.b64 %0, {%1, %1};" : "=l"(xx) : "f"(x));
                asm("fma.rn.f32x2 %0, %1, %2, %0;" : "+l"(acc0[r]) : "l"(xx), "l"(wp.x));
                asm("fma.rn.f32x2 %0, %1, %2, %0;" : "+l"(acc1[r]) : "l"(xx), "l"(wp.y));
            }
        }
    }

    float4 aL = *(const float4*)&a[c4];
    float4 aH = *(const float4*)&a[DD + c4];
#pragma unroll
    for (int r = 0; r < 8; ++r) {
        int row = base + r0 + r;
        if (row >= n) break;          // uniform across warp
        float4 c;
        asm("mov.b64 {%0, %1}, %2;" : "=f"(c.x), "=f"(c.y) : "l"(acc0[r]));
        asm("mov.b64 {%0, %1}, %2;" : "=f"(c.z), "=f"(c.w) : "l"(acc1[r]));
        *(float4*)&g_h[row * DD + c4] = c;
        float ps = c.x * aL.x + c.y * aL.y + c.z * aL.z + c.w * aL.w;
        float pd = c.x * aH.x + c.y * aH.y + c.z * aH.z + c.w * aH.w;
#pragma unroll
        for (int o = 16; o > 0; o >>= 1) {
            ps += __shfl_xor_sync(0xffffffff, ps, o);
            pd += __shfl_xor_sync(0xffffffff, pd, o);
        }
        if (lane == 0) { g_ssrc[row] = ps; g_sdst[row] = pd; }
    }
}

// ---------------- degree histogram (4 edges/thread for MLP) ----------------
__global__ void hist_kernel(const int* __restrict__ e32, int E) {
    const int mult = detect_is64_block(e32, E) ? 2 : 1;
    int i0 = (blockIdx.x * blockDim.x + threadIdx.x) * 4;
    int s[4];
#pragma unroll
    for (int j = 0; j < 4; ++j) {
        int i = i0 + j;
        s[j] = (i < E) ? e32[(long long)i * mult] : -1;
    }
#pragma unroll
    for (int j = 0; j < 4; ++j)
        if (s[j] >= 0) atomicAdd(&g_deg[s[j]], 1);
}

// ---------------- 2-pass exclusive scan over g_deg -------------------------
__global__ void scan1_kernel(int n) {
    const int tid = threadIdx.x;
    const int lane = tid & 31, wid = tid >> 5;
    int i = blockIdx.x * 256 + tid;
    int v = (i < n) ? g_deg[i] : 0;
    int s = v;
#pragma unroll
    for (int off = 1; off < 32; off <<= 1) {
        int t = __shfl_up_sync(0xffffffffu, s, off);
        if (lane >= off) s += t;
    }
    __shared__ int wtot[8], woff[8];
    if (lane == 31) wtot[wid] = s;
    __syncthreads();
    if (tid == 0) {
        int run = 0;
#pragma unroll
        for (int w = 0; w < 8; ++w) { woff[w] = run; run += wtot[w]; }
        g_part[blockIdx.x] = run;
        if (blockIdx.x == 0) g_rowptr[0] = 0;
    }
    __syncthreads();
    if (i < n) g_rowptr[i + 1] = s + woff[wid];   // block-local inclusive
}

// scan2+scan3 fused: every block redundantly scans the <=256 block partials,
// applies its exclusive offset, emits cursor, and RE-ZEROS g_deg for the
// next call (maintains the all-zero invariant established at module load).
__global__ void scan23_kernel(int n, int nb) {
    const int tid = threadIdx.x;
    const int lane = tid & 31, wid = tid >> 5;
    int v = (tid < nb) ? g_part[tid] : 0;
    int s = v;
#pragma unroll
    for (int off = 1; off < 32; off <<= 1) {
        int t = __shfl_up_sync(0xffffffffu, s, off);
        if (lane >= off) s += t;
    }
    __shared__ int wtot[8], woff[8];
    __shared__ int sh_excl[256];
    if (lane == 31) wtot[wid] = s;
    __syncthreads();
    if (tid == 0) {
        int run = 0;
#pragma unroll
        for (int w = 0; w < 8; ++w) { woff[w] = run; run += wtot[w]; }
    }
    __syncthreads();
    sh_excl[tid] = s - v + woff[wid];             // exclusive offsets
    __syncthreads();
    int blockOff = sh_excl[blockIdx.x];
    int i = blockIdx.x * 256 + tid;
    if (i < n) {
        int incl = g_rowptr[i + 1] + blockOff;
        g_rowptr[i + 1] = incl;
        g_cursor[i] = incl - g_deg[i];
        g_deg[i] = 0;                             // restore invariant
    }
}

// ---------------- scatter dst into CSR slots (4 edges/thread) --------------
__global__ void scatter_kernel(const int* __restrict__ e32, int E) {
    const int mult = detect_is64_block(e32, E) ? 2 : 1;
    int i0 = (blockIdx.x * blockDim.x + threadIdx.x) * 4;
    int s[4], d[4];
#pragma unroll
    for (int j = 0; j < 4; ++j) {
        int i = i0 + j;
        if (i < E) {
            s[j] = e32[(long long)i * mult];
            d[j] = e32[(long long)(E + i) * mult];
        } else s[j] = -1;
    }
#pragma unroll
    for (int j = 0; j < 4; ++j) {
        if (s[j] >= 0) {
            int p = atomicAdd(&g_cursor[s[j]], 1);
            g_edst[p] = d[j];
        }
    }
}

// ---------------- gather: warp/node, on-the-fly weights, 4x unroll, ELU ----
__global__ void gather_kernel(float* __restrict__ out, int n) {
    int gw = (blockIdx.x * blockDim.x + threadIdx.x) >> 5;
    int lane = threadIdx.x & 31;
    if (gw >= n) return;
    int beg = g_rowptr[gw], end = g_rowptr[gw + 1];
    float ss = g_ssrc[gw];
    float4 acc0 = make_float4(0.f, 0.f, 0.f, 0.f);
    float4 acc1 = make_float4(0.f, 0.f, 0.f, 0.f);
    float4 acc2 = make_float4(0.f, 0.f, 0.f, 0.f);
    float4 acc3 = make_float4(0.f, 0.f, 0.f, 0.f);
    float rs = 0.f;
    int p = beg;
    for (; p + 4 <= end; p += 4) {
        int d0 = g_edst[p];                      // broadcast
        int d1 = g_edst[p + 1];
        int d2 = g_edst[p + 2];
        int d3 = g_edst[p + 3];
        float4 h0 = *(const float4*)&g_h[d0 * DD + lane * 4];
        float4 h1 = *(const float4*)&g_h[d1 * DD + lane * 4];
        float4 h2 = *(const float4*)&g_h[d2 * DD + lane * 4];
        float4 h3 = *(const float4*)&g_h[d3 * DD + lane * 4];
        float sc0 = ss + g_sdst[d0];
        float sc1 = ss + g_sdst[d1];
        float sc2 = ss + g_sdst[d2];
        float sc3 = ss + g_sdst[d3];
        float e0 = expf(sc0 > 0.f ? sc0 : ALPHA * sc0);
        float e1 = expf(sc1 > 0.f ? sc1 : ALPHA * sc1);
        float e2 = expf(sc2 > 0.f ? sc2 : ALPHA * sc2);
        float e3 = expf(sc3 > 0.f ? sc3 : ALPHA * sc3);
        acc0.x += e0 * h0.x; acc0.y += e0 * h0.y;
        acc0.z += e0 * h0.z; acc0.w += e0 * h0.w;
        acc1.x += e1 * h1.x; acc1.y += e1 * h1.y;
        acc1.z += e1 * h1.z; acc1.w += e1 * h1.w;
        acc2.x += e2 * h2.x; acc2.y += e2 * h2.y;
        acc2.z += e2 * h2.z; acc2.w += e2 * h2.w;
        acc3.x += e3 * h3.x; acc3.y += e3 * h3.y;
        acc3.z += e3 * h3.z; acc3.w += e3 * h3.w;
        rs += e0 + e1 + e2 + e3;
    }
    for (; p < end; ++p) {
        int d = g_edst[p];
        float sc = ss + g_sdst[d];
        float e = expf(sc > 0.f ? sc : ALPHA * sc);
        float4 hv = *(const float4*)&g_h[d * DD + lane * 4];
        acc0.x += e * hv.x; acc0.y += e * hv.y;
        acc0.z += e * hv.z; acc0.w += e * hv.w;
        rs += e;
    }
    float inv = 1.0f / rs;
    float4 o;
    float vx = (acc0.x + acc1.x + acc2.x + acc3.x) * inv; o.x = vx > 0.f ? vx : (expf(vx) - 1.0f);
    float vy = (acc0.y + acc1.y + acc2.y + acc3.y) * inv; o.y = vy > 0.f ? vy : (expf(vy) - 1.0f);
    float vz = (acc0.z + acc1.z + acc2.z + acc3.z) * inv; o.z = vz > 0.f ? vz : (expf(vz) - 1.0f);
    float vw = (acc0.w + acc1.w + acc2.w + acc3.w) * inv; o.w = vw > 0.f ? vw : (expf(vw) - 1.0f);
    *(float4*)&out[gw * DD + lane * 4] = o;
}

// ---------------- launch ----------------
extern "C" void kernel_launch(void* const* d_in, const int* in_sizes, int n_in,
                              void* d_out, int out_size) {
    const float* X   = (const float*)d_in[0];
    const int*   e32 = (const int*)d_in[1];   // int32 or int64, detected per-block
    const float* W   = (const float*)d_in[2];
    const float* a   = (const float*)d_in[3];
    float* out = (float*)d_out;

    int n = in_sizes[0] / DD;
    int E = in_sizes[1] / 2;
    int nb = (n + 255) / 256;

    const int smem_bytes = (DD * DD + TR * DD) * (int)sizeof(float);  // 96KB
    cudaFuncSetAttribute(gemm_kernel, cudaFuncAttributeMaxDynamicSharedMemorySize, smem_bytes);

    // Fork: CSR-build chain (independent of GEMM) runs on side stream.
    cudaEventRecord(g_evFork, 0);
    cudaStreamWaitEvent(g_s2, g_evFork, 0);

    hist_kernel   <<<(E + 1023) / 1024, 256, 0, g_s2>>>(e32, E);
    scan1_kernel  <<<nb, 256, 0, g_s2>>>(n);
    scan23_kernel <<<nb, 256, 0, g_s2>>>(n, nb);
    scatter_kernel<<<(E + 1023) / 1024, 256, 0, g_s2>>>(e32, E);
    cudaEventRecord(g_evJoin, g_s2);

    // Main stream: GEMM overlaps the CSR build.
    gemm_kernel<<<(n + TR - 1) / TR, 256, smem_bytes>>>(X, W, a, n);

    // Join, then gather (needs both h/scores and CSR).
    cudaStreamWaitEvent(0, g_evJoin, 0);
    gather_kernel<<<((long long)n * 32 + 255) / 256, 256>>>(out, n);
}

// round 17
// speedup vs baseline: 1.0593x; 1.0593x over previous
#include <cuda_runtime.h>
#include <math.h>

#define NMAX 50000
#define DD 128
#define EMAX 700000
#define TR 64            // GEMM rows per block
#define ALPHA 0.2f

// ---------------- scratch (device globals, no runtime alloc) ----------------
// g_deg zero at module load; scan_kernel re-zeros it after last read.
// g_state zeroed by hist_kernel before scan_kernel runs (same stream).
__device__ float g_h[NMAX * DD];      // h = X @ W
__device__ float g_ssrc[NMAX];        // h . a[:D]
__device__ float g_sdst[NMAX];        // h . a[D:]
__device__ int   g_deg[NMAX];
__device__ int   g_rowptr[NMAX + 1];
__device__ int   g_cursor[NMAX];
__device__ int   g_edst[EMAX];        // CSR-sorted dst
__device__ unsigned long long g_state[256];  // decoupled-lookback: (val<<2)|flag
__device__ int   g_mult;              // 1 = int32 edges, 2 = int64 edges

// ---------------- side stream + fork/join events (created once, pre-main) --
static cudaStream_t g_s2;
static cudaEvent_t  g_evFork, g_evJoin;
static struct StreamInit {
    StreamInit() {
        cudaStreamCreateWithFlags(&g_s2, cudaStreamNonBlocking);
        cudaEventCreateWithFlags(&g_evFork, cudaEventDisableTiming);
        cudaEventCreateWithFlags(&g_evJoin, cudaEventDisableTiming);
    }
} g_streamInit;

// ---------------- GEMM + attention projections (packed f32x2 FFMA) ----------
__global__ void __launch_bounds__(256, 2)
gemm_kernel(const float* __restrict__ X, const float* __restrict__ W,
            const float* __restrict__ a, int n) {
    extern __shared__ float smem[];
    float* Ws = smem;                 // 128*128
    float* Xs = smem + DD * DD;       // 64*128
    const int base = blockIdx.x * TR;
    const int tid = threadIdx.x;

    for (int i = tid * 4; i < DD * DD; i += blockDim.x * 4)
        *(float4*)&Ws[i] = *(const float4*)&W[i];
    for (int i = tid * 4; i < TR * DD; i += blockDim.x * 4) {
        int row = base + i / DD;
        float4 v = make_float4(0.f, 0.f, 0.f, 0.f);
        if (row < n) v = *(const float4*)&X[row * DD + (i % DD)];
        *(float4*)&Xs[i] = v;
    }
    __syncthreads();

    const int lane = tid & 31;
    const int wid = tid >> 5;         // 8 warps
    const int c4 = lane * 4;
    const int r0 = wid * 8;

    unsigned long long acc0[8], acc1[8];
#pragma unroll
    for (int r = 0; r < 8; ++r) { acc0[r] = 0ull; acc1[r] = 0ull; }

    for (int k = 0; k < DD; k += 4) {
        float4 xv[8];
#pragma unroll
        for (int r = 0; r < 8; ++r)
            xv[r] = *(const float4*)&Xs[(r0 + r) * DD + k];
#pragma unroll
        for (int kk = 0; kk < 4; ++kk) {
            ulonglong2 wp = *(const ulonglong2*)&Ws[(k + kk) * DD + c4];
#pragma unroll
            for (int r = 0; r < 8; ++r) {
                float x = (kk == 0) ? xv[r].x : (kk == 1) ? xv[r].y
                         : (kk == 2) ? xv[r].z : xv[r].w;
                unsigned long long xx;
                asm("mov.b64 %0, {%1, %1};" : "=l"(xx) : "f"(x));
                asm("fma.rn.f32x2 %0, %1, %2, %0;" : "+l"(acc0[r]) : "l"(xx), "l"(wp.x));
                asm("fma.rn.f32x2 %0, %1, %2, %0;" : "+l"(acc1[r]) : "l"(xx), "l"(wp.y));
            }
        }
    }

    float4 aL = *(const float4*)&a[c4];
    float4 aH = *(const float4*)&a[DD + c4];
#pragma unroll
    for (int r = 0; r < 8; ++r) {
        int row = base + r0 + r;
        if (row >= n) break;
        float4 c;
        asm("mov.b64 {%0, %1}, %2;" : "=f"(c.x), "=f"(c.y) : "l"(acc0[r]));
        asm("mov.b64 {%0, %1}, %2;" : "=f"(c.z), "=f"(c.w) : "l"(acc1[r]));
        *(float4*)&g_h[row * DD + c4] = c;
        float ps = c.x * aL.x + c.y * aL.y + c.z * aL.z + c.w * aL.w;
        float pd = c.x * aH.x + c.y * aH.y + c.z * aH.z + c.w * aH.w;
#pragma unroll
        for (int o = 16; o > 0; o >>= 1) {
            ps += __shfl_xor_sync(0xffffffff, ps, o);
            pd += __shfl_xor_sync(0xffffffff, pd, o);
        }
        if (lane == 0) { g_ssrc[row] = ps; g_sdst[row] = pd; }
    }
}

// ---------------- degree histogram (8 edges/thread) + detect + state zero --
__global__ void hist_kernel(const int* __restrict__ e32, int E) {
    // zero scan lookback state (stream-ordered before scan_kernel)
    if (blockIdx.x == 0 && threadIdx.x < 256) g_state[threadIdx.x] = 0ull;

    // int64 little-endian => odd 32-bit words are high halves (zero for ids
    // < 2^31). For int32 they are random node ids: 32 consecutive zeros is
    // impossible. Warp 0 decides, shared-broadcasts.
    __shared__ int s_mult;
    if (threadIdx.x < 32) {
        int j = 2 * (int)threadIdx.x + 1;
        int v = (j < 2 * E) ? e32[j] : 0;
        unsigned nz = __ballot_sync(0xffffffffu, v != 0);
        if (threadIdx.x == 0) {
            s_mult = (nz == 0) ? 2 : 1;
            if (blockIdx.x == 0) g_mult = s_mult;
        }
    }
    __syncthreads();
    const int mult = s_mult;

    int i0 = (blockIdx.x * blockDim.x + threadIdx.x) * 8;
    int s[8];
#pragma unroll
    for (int j = 0; j < 8; ++j) {
        int i = i0 + j;
        s[j] = (i < E) ? e32[(long long)i * mult] : -1;
    }
#pragma unroll
    for (int j = 0; j < 8; ++j)
        if (s[j] >= 0) atomicAdd(&g_deg[s[j]], 1);
}

// ---------------- single-pass scan: decoupled lookback ----------------------
// One launch replaces scan1 + scan23. Block bid: local inclusive scan of its
// 256 degrees; publish (aggregate<<2)|flag atomically (flag 1=aggregate,
// 2=inclusive prefix); warp 0 looks back, 32 predecessors per round.
__global__ void scan_kernel(int n) {
    const int tid = threadIdx.x;
    const int lane = tid & 31, wid = tid >> 5;
    const int bid = blockIdx.x;
    int i = bid * 256 + tid;
    int v = (i < n) ? g_deg[i] : 0;
    int s = v;
#pragma unroll
    for (int off = 1; off < 32; off <<= 1) {
        int t = __shfl_up_sync(0xffffffffu, s, off);
        if (lane >= off) s += t;
    }
    __shared__ int wtot[8], woff[8], s_agg;
    __shared__ long long s_run;
    if (lane == 31) wtot[wid] = s;
    __syncthreads();
    if (tid == 0) {
        int run = 0;
#pragma unroll
        for (int w = 0; w < 8; ++w) { woff[w] = run; run += wtot[w]; }
        s_agg = run;
        s_run = 0;
        unsigned long long st = ((unsigned long long)run << 2) | (bid == 0 ? 2u : 1u);
        atomicExch(&g_state[bid], st);
        if (bid == 0) g_rowptr[0] = 0;
    }
    __syncthreads();

    if (bid > 0 && wid == 0) {
        long long run = 0;
        int base = bid - 1;
        for (;;) {
            int idx = base - lane;            // lane 0 = nearest predecessor
            unsigned long long st = 0;
            if (idx >= 0) {
                volatile unsigned long long* p = &g_state[idx];
                do { st = *p; } while ((st & 3ull) == 0ull);
            }
            unsigned m2 = __ballot_sync(0xffffffffu, idx >= 0 && (st & 3ull) == 2ull);
            if (m2) {
                int fl = __ffs(m2) - 1;       // nearest inclusive-prefix block
                long long c = (idx >= 0 && lane <= fl) ? (long long)(st >> 2) : 0;
#pragma unroll
                for (int o = 16; o > 0; o >>= 1)
                    c += __shfl_xor_sync(0xffffffffu, c, o);
                run += c;
                break;
            } else {
                long long c = (idx >= 0) ? (long long)(st >> 2) : 0;
#pragma unroll
                for (int o = 16; o > 0; o >>= 1)
                    c += __shfl_xor_sync(0xffffffffu, c, o);
                run += c;
                base -= 32;
                if (base < 0) break;          // unreachable: block 0 is flag-2
            }
        }
        if (lane == 0) {
            s_run = run;
            unsigned long long tot = (unsigned long long)(run + s_agg);
            atomicExch(&g_state[bid], (tot << 2) | 2ull);   // unblock successors
        }
    }
    __syncthreads();
    int blockOff = (int)s_run;
    if (i < n) {
        int incl = s + woff[wid] + blockOff;
        g_rowptr[i + 1] = incl;
        g_cursor[i] = incl - v;
        g_deg[i] = 0;                         // restore invariant for next call
    }
}

// ---------------- scatter dst into CSR slots (8 edges/thread) --------------
__global__ void scatter_kernel(const int* __restrict__ e32, int E) {
    const int mult = g_mult;                  // written by hist (stream-ordered)
    int i0 = (blockIdx.x * blockDim.x + threadIdx.x) * 8;
    int s[8], d[8];
#pragma unroll
    for (int j = 0; j < 8; ++j) {
        int i = i0 + j;
        if (i < E) {
            s[j] = e32[(long long)i * mult];
            d[j] = e32[(long long)(E + i) * mult];
        } else s[j] = -1;
    }
#pragma unroll
    for (int j = 0; j < 8; ++j) {
        if (s[j] >= 0) {
            int p = atomicAdd(&g_cursor[s[j]], 1);
            g_edst[p] = d[j];
        }
    }
}

// ---------------- gather: warp/node, on-the-fly weights, 4x unroll, ELU ----
__global__ void gather_kernel(float* __restrict__ out, int n) {
    int gw = (blockIdx.x * blockDim.x + threadIdx.x) >> 5;
    int lane = threadIdx.x & 31;
    if (gw >= n) return;
    int beg = g_rowptr[gw], end = g_rowptr[gw + 1];
    float ss = g_ssrc[gw];
    float4 acc0 = make_float4(0.f, 0.f, 0.f, 0.f);
    float4 acc1 = make_float4(0.f, 0.f, 0.f, 0.f);
    float4 acc2 = make_float4(0.f, 0.f, 0.f, 0.f);
    float4 acc3 = make_float4(0.f, 0.f, 0.f, 0.f);
    float rs = 0.f;
    int p = beg;
    for (; p + 4 <= end; p += 4) {
        int d0 = g_edst[p];
        int d1 = g_edst[p + 1];
        int d2 = g_edst[p + 2];
        int d3 = g_edst[p + 3];
        float4 h0 = *(const float4*)&g_h[d0 * DD + lane * 4];
        float4 h1 = *(const float4*)&g_h[d1 * DD + lane * 4];
        float4 h2 = *(const float4*)&g_h[d2 * DD + lane * 4];
        float4 h3 = *(const float4*)&g_h[d3 * DD + lane * 4];
        float sc0 = ss + g_sdst[d0];
        float sc1 = ss + g_sdst[d1];
        float sc2 = ss + g_sdst[d2];
        float sc3 = ss + g_sdst[d3];
        float e0 = __expf(sc0 > 0.f ? sc0 : ALPHA * sc0);
        float e1 = __expf(sc1 > 0.f ? sc1 : ALPHA * sc1);
        float e2 = __expf(sc2 > 0.f ? sc2 : ALPHA * sc2);
        float e3 = __expf(sc3 > 0.f ? sc3 : ALPHA * sc3);
        acc0.x += e0 * h0.x; acc0.y += e0 * h0.y;
        acc0.z += e0 * h0.z; acc0.w += e0 * h0.w;
        acc1.x += e1 * h1.x; acc1.y += e1 * h1.y;
        acc1.z += e1 * h1.z; acc1.w += e1 * h1.w;
        acc2.x += e2 * h2.x; acc2.y += e2 * h2.y;
        acc2.z += e2 * h2.z; acc2.w += e2 * h2.w;
        acc3.x += e3 * h3.x; acc3.y += e3 * h3.y;
        acc3.z += e3 * h3.z; acc3.w += e3 * h3.w;
        rs += e0 + e1 + e2 + e3;
    }
    for (; p < end; ++p) {
        int d = g_edst[p];
        float sc = ss + g_sdst[d];
        float e = __expf(sc > 0.f ? sc : ALPHA * sc);
        float4 hv = *(const float4*)&g_h[d * DD + lane * 4];
        acc0.x += e * hv.x; acc0.y += e * hv.y;
        acc0.z += e * hv.z; acc0.w += e * hv.w;
        rs += e;
    }
    float inv = 1.0f / rs;
    float4 o;
    float vx = (acc0.x + acc1.x + acc2.x + acc3.x) * inv; o.x = vx > 0.f ? vx : (__expf(vx) - 1.0f);
    float vy = (acc0.y + acc1.y + acc2.y + acc3.y) * inv; o.y = vy > 0.f ? vy : (__expf(vy) - 1.0f);
    float vz = (acc0.z + acc1.z + acc2.z + acc3.z) * inv; o.z = vz > 0.f ? vz : (__expf(vz) - 1.0f);
    float vw = (acc0.w + acc1.w + acc2.w + acc3.w) * inv; o.w = vw > 0.f ? vw : (__expf(vw) - 1.0f);
    *(float4*)&out[gw * DD + lane * 4] = o;
}

// ---------------- launch ----------------
extern "C" void kernel_launch(void* const* d_in, const int* in_sizes, int n_in,
                              void* d_out, int out_size) {
    const float* X   = (const float*)d_in[0];
    const int*   e32 = (const int*)d_in[1];   // int32 or int64, detected on device
    const float* W   = (const float*)d_in[2];
    const float* a   = (const float*)d_in[3];
    float* out = (float*)d_out;

    int n = in_sizes[0] / DD;
    int E = in_sizes[1] / 2;
    int nb = (n + 255) / 256;
    int eb = (E + 2047) / 2048;               // 8 edges/thread, 256 threads

    const int smem_bytes = (DD * DD + TR * DD) * (int)sizeof(float);  // 96KB
    cudaFuncSetAttribute(gemm_kernel, cudaFuncAttributeMaxDynamicSharedMemorySize, smem_bytes);

    // Fork: CSR-build chain (independent of GEMM) runs on side stream.
    cudaEventRecord(g_evFork, 0);
    cudaStreamWaitEvent(g_s2, g_evFork, 0);

    hist_kernel   <<<eb, 256, 0, g_s2>>>(e32, E);
    scan_kernel   <<<nb, 256, 0, g_s2>>>(n);
    scatter_kernel<<<eb, 256, 0, g_s2>>>(e32, E);
    cudaEventRecord(g_evJoin, g_s2);

    // Main stream: GEMM overlaps the CSR build.
    gemm_kernel<<<(n + TR - 1) / TR, 256, smem_bytes>>>(X, W, a, n);

    // Join, then gather (needs both h/scores and CSR).
    cudaStreamWaitEvent(0, g_evJoin, 0);
    gather_kernel<<<((long long)n * 32 + 255) / 256, 256>>>(out, n);
}